// round 2
// baseline (speedup 1.0000x reference)
#include <cuda_runtime.h>

#define T_STEPS 800
#define B_DIM   128
#define S_DIM   500
#define M_DIM   (T_STEPS * B_DIM)   /* 102400 */
#define BS      (B_DIM * S_DIM)     /* 64000  */
#define TBS     (T_STEPS * BS)      /* 51.2M  */

/* scratch: total[t,b,s] = input - error @ W^T  (204.8 MB) */
__device__ float g_total[(size_t)T_STEPS * B_DIM * S_DIM];

/* ------------------------------------------------------------------ */
/* GEMM: g_total[m,n] = inp[m,n] - sum_k err[m,k] * W[n,k]            */
/* m in [0,102400), n,k in [0,500). Both operands K-contiguous.       */
/* ------------------------------------------------------------------ */
#define BM 128
#define BN 128
#define BK 8
#define TM 8
#define TN 8

__global__ __launch_bounds__(256)
void spncn_gemm_kernel(const float* __restrict__ err,
                       const float* __restrict__ W,
                       const float* __restrict__ inp)
{
    __shared__ float As[BK][BM];
    __shared__ float Bs[BK][BN];

    const int tid    = threadIdx.x;
    const int blockM = blockIdx.y * BM;
    const int blockN = blockIdx.x * BN;
    const int trow   = (tid / 16) * TM;   /* 0,8,...,120 */
    const int tcol   = (tid % 16) * TN;

    float acc[TM][TN];
#pragma unroll
    for (int i = 0; i < TM; i++)
#pragma unroll
        for (int j = 0; j < TN; j++) acc[i][j] = 0.0f;

    for (int k0 = 0; k0 < S_DIM; k0 += BK) {
        /* load err tile (BM x BK), store transposed As[k][m] */
#pragma unroll
        for (int i = 0; i < 4; i++) {
            int idx = tid + i * 256;
            int m   = idx >> 3;
            int k   = idx & 7;
            int gk  = k0 + k;
            float v = 0.0f;
            if (gk < S_DIM) v = err[(size_t)(blockM + m) * S_DIM + gk];
            As[k][m] = v;
        }
        /* load W tile (BN x BK), store transposed Bs[k][n] */
#pragma unroll
        for (int i = 0; i < 4; i++) {
            int idx = tid + i * 256;
            int n   = idx >> 3;
            int k   = idx & 7;
            int gk  = k0 + k;
            int gn  = blockN + n;
            float v = 0.0f;
            if (gk < S_DIM && gn < S_DIM) v = W[(size_t)gn * S_DIM + gk];
            Bs[k][n] = v;
        }
        __syncthreads();

#pragma unroll
        for (int k = 0; k < BK; k++) {
            float ra[TM], rb[TN];
#pragma unroll
            for (int i = 0; i < TM; i++) ra[i] = As[k][trow + i];
#pragma unroll
            for (int j = 0; j < TN; j++) rb[j] = Bs[k][tcol + j];
#pragma unroll
            for (int i = 0; i < TM; i++)
#pragma unroll
                for (int j = 0; j < TN; j++)
                    acc[i][j] += ra[i] * rb[j];
        }
        __syncthreads();
    }

    /* epilogue: total = inp - acc */
#pragma unroll
    for (int i = 0; i < TM; i++) {
        int m = blockM + trow + i;
#pragma unroll
        for (int j = 0; j < TN; j++) {
            int n = blockN + tcol + j;
            if (n < S_DIM) {
                size_t off = (size_t)m * S_DIM + n;
                g_total[off] = inp[off] - acc[i][j];
            }
        }
    }
}

/* ------------------------------------------------------------------ */
/* Sequential scan over T per (b,s) element.                          */
/*   reset = H(mem - thr)   (on previous mem)                         */
/*   syn   = alpha*syn + total                                        */
/*   mem   = (beta*mem + syn) * (1 - reset)                           */
/*   spk   = H(mem - thr)                                             */
/*   trace = kappa*trace + spk                                        */
/* out[0:TBS) = spikes, out[TBS:2*TBS) = traces                       */
/* ------------------------------------------------------------------ */
__global__ __launch_bounds__(128)
void spncn_scan_kernel(float* __restrict__ out)
{
    const int i = blockIdx.x * blockDim.x + threadIdx.x;
    if (i >= BS) return;

    const float ALPHA = (float)(1.0 - 0.25 / 10.0);
    const float BETA  = (float)(1.0 - 0.25 / 20.0);
    const float KAPPA = (float)(1.0 - 0.25 / 30.0);
    const float THR   = 0.4f;

    float syn = 0.0f, mem = 0.0f, tr = 0.0f;
    const float* __restrict__ tot = g_total + i;
    float* __restrict__ o_spk = out + i;
    float* __restrict__ o_tr  = out + TBS + i;

#pragma unroll 1
    for (int t = 0; t < T_STEPS; t += 4) {
        /* batch 4 loads for MLP */
        float in0 = tot[(t + 0) * BS];
        float in1 = tot[(t + 1) * BS];
        float in2 = tot[(t + 2) * BS];
        float in3 = tot[(t + 3) * BS];

#define STEP(tt, inv)                                          \
        {                                                      \
            float reset = ((mem - THR) > 0.0f) ? 1.0f : 0.0f;  \
            syn = ALPHA * syn + (inv);                         \
            mem = BETA * mem + syn;                            \
            if (reset != 0.0f) mem = 0.0f;                     \
            float spk = ((mem - THR) > 0.0f) ? 1.0f : 0.0f;    \
            tr = KAPPA * tr + spk;                             \
            o_spk[(tt) * BS] = spk;                            \
            o_tr[(tt) * BS]  = tr;                             \
        }

        STEP(t + 0, in0)
        STEP(t + 1, in1)
        STEP(t + 2, in2)
        STEP(t + 3, in3)
#undef STEP
    }
}

/* ------------------------------------------------------------------ */
extern "C" void kernel_launch(void* const* d_in, const int* in_sizes, int n_in,
                              void* d_out, int out_size)
{
    const float* input_signal = (const float*)d_in[0];
    const float* error_signal = (const float*)d_in[1];
    const float* W_err        = (const float*)d_in[2];
    float* out = (float*)d_out;

    dim3 gemm_grid((S_DIM + BN - 1) / BN, M_DIM / BM);  /* 4 x 800 */
    spncn_gemm_kernel<<<gemm_grid, 256>>>(error_signal, W_err, input_signal);

    spncn_scan_kernel<<<(BS + 127) / 128, 128>>>(out);
}

// round 4
// speedup vs baseline: 1.1854x; 1.1854x over previous
#include <cuda_runtime.h>

#define T_STEPS 800
#define B_DIM   128
#define S_DIM   500
#define M_DIM   (T_STEPS * B_DIM)   /* 102400 */
#define BS      (B_DIM * S_DIM)     /* 64000  */
#define TBS     (T_STEPS * BS)      /* 51.2M  */

typedef unsigned long long u64;

/* scratch: total[t,b,s] = input - error @ W^T  (204.8 MB) */
__device__ float g_total[(size_t)T_STEPS * B_DIM * S_DIM];

__device__ __forceinline__ u64 ffma2(u64 a, u64 b, u64 c)
{
    u64 d;
    asm("fma.rn.f32x2 %0, %1, %2, %3;" : "=l"(d) : "l"(a), "l"(b), "l"(c));
    return d;
}

/* ------------------------------------------------------------------ */
/* GEMM: g_total[m,n] = inp[m,n] - sum_k err[m,k] * W[n,k]            */
/* BM=128, BN=128, BK=8; 256 threads; 8x8 per-thread tile computed    */
/* as 4 m-pairs x 8 n via packed fma.rn.f32x2 (FFMA2).                */
/* ------------------------------------------------------------------ */
#define BM 128
#define BN 128
#define BK 8
#define NKT 63   /* ceil(500/8) */

__global__ __launch_bounds__(256, 2)
void spncn_gemm_kernel(const float* __restrict__ err,
                       const float* __restrict__ W,
                       const float* __restrict__ inp)
{
    __shared__ float  As[BK][BM];     /* As[k][m] = err[blockM+m][k0+k]          */
    __shared__ float2 Bs[BK][BN];     /* Bs[k][n] = dup(W[blockN+n][k0+k])       */

    const int tid    = threadIdx.x;
    const int blockM = blockIdx.y * BM;
    const int blockN = blockIdx.x * BN;
    const int r      = tid >> 4;      /* 0..15 : m-pair group */
    const int c      = tid & 15;      /* 0..15 : n group      */

    /* fill mapping: each thread loads 2 float2 (4 k) for one m-row / n-row */
    const int am  = tid & 127;            /* row within tile        */
    const int akp = (tid >> 7) * 2;       /* float2 index base: 0|2 */
    const int gm  = blockM + am;
    const int gn  = blockN + am;
    const bool n_ok = (gn < S_DIM);

    u64 acc[4][8];
#pragma unroll
    for (int i = 0; i < 4; i++)
#pragma unroll
        for (int j = 0; j < 8; j++) acc[i][j] = 0ull;

    float2 pa[2], pw[2];

    /* prefetch tile 0 */
#pragma unroll
    for (int q = 0; q < 2; q++) {
        int k = (akp + q) * 2;            /* k0 = 0 */
        pa[q] = make_float2(0.f, 0.f);
        pw[q] = make_float2(0.f, 0.f);
        if (k < S_DIM)
            pa[q] = *(const float2*)(err + (size_t)gm * S_DIM + k);
        if (n_ok && k < S_DIM)
            pw[q] = *(const float2*)(W + (size_t)gn * S_DIM + k);
    }

    for (int t = 0; t < NKT; t++) {
        /* store prefetched regs into smem */
#pragma unroll
        for (int q = 0; q < 2; q++) {
            int kl = (akp + q) * 2;
            As[kl][am]     = pa[q].x;
            As[kl + 1][am] = pa[q].y;
            Bs[kl][am]     = make_float2(pw[q].x, pw[q].x);
            Bs[kl + 1][am] = make_float2(pw[q].y, pw[q].y);
        }
        __syncthreads();

        /* prefetch next tile */
        if (t + 1 < NKT) {
            int k0n = (t + 1) * BK;
#pragma unroll
            for (int q = 0; q < 2; q++) {
                int k = k0n + (akp + q) * 2;
                pa[q] = make_float2(0.f, 0.f);
                pw[q] = make_float2(0.f, 0.f);
                if (k < S_DIM)
                    pa[q] = *(const float2*)(err + (size_t)gm * S_DIM + k);
                if (n_ok && k < S_DIM)
                    pw[q] = *(const float2*)(W + (size_t)gn * S_DIM + k);
            }
        }

        /* compute BK k-steps */
#pragma unroll
        for (int k = 0; k < BK; k++) {
            u64 ra[4], rb[8];
#pragma unroll
            for (int ip = 0; ip < 4; ip++)
                ra[ip] = *(const u64*)&As[k][2 * (r + 16 * ip)];
#pragma unroll
            for (int j = 0; j < 8; j++)
                rb[j] = *(const u64*)&Bs[k][c + 16 * j];
#pragma unroll
            for (int ip = 0; ip < 4; ip++)
#pragma unroll
                for (int j = 0; j < 8; j++)
                    acc[ip][j] = ffma2(ra[ip], rb[j], acc[ip][j]);
        }
        __syncthreads();
    }

    /* epilogue: total = inp - acc */
#pragma unroll
    for (int ip = 0; ip < 4; ip++) {
        int m0 = blockM + 2 * (r + 16 * ip);
#pragma unroll
        for (int j = 0; j < 8; j++) {
            int n = blockN + c + 16 * j;
            if (n < S_DIM) {
                float2 v = *(float2*)&acc[ip][j];
                size_t o0 = (size_t)m0 * S_DIM + n;
                size_t o1 = o0 + S_DIM;
                g_total[o0] = inp[o0] - v.x;
                g_total[o1] = inp[o1] - v.y;
            }
        }
    }
}

/* ------------------------------------------------------------------ */
/* Sequential scan over T per (b,s) element.                          */
/* ------------------------------------------------------------------ */
__global__ __launch_bounds__(128)
void spncn_scan_kernel(float* __restrict__ out)
{
    const int i = blockIdx.x * blockDim.x + threadIdx.x;
    if (i >= BS) return;

    const float ALPHA = (float)(1.0 - 0.25 / 10.0);
    const float BETA  = (float)(1.0 - 0.25 / 20.0);
    const float KAPPA = (float)(1.0 - 0.25 / 30.0);
    const float THR   = 0.4f;

    float syn = 0.0f, mem = 0.0f, tr = 0.0f;
    const float* __restrict__ tot = g_total + i;
    float* __restrict__ o_spk = out + i;
    float* __restrict__ o_tr  = out + TBS + i;

#pragma unroll 1
    for (int t = 0; t < T_STEPS; t += 8) {
        float in[8];
#pragma unroll
        for (int q = 0; q < 8; q++) in[q] = tot[(size_t)(t + q) * BS];

#pragma unroll
        for (int q = 0; q < 8; q++) {
            float reset = ((mem - THR) > 0.0f) ? 1.0f : 0.0f;
            syn = ALPHA * syn + in[q];
            mem = BETA * mem + syn;
            if (reset != 0.0f) mem = 0.0f;
            float spk = ((mem - THR) > 0.0f) ? 1.0f : 0.0f;
            tr = KAPPA * tr + spk;
            o_spk[(size_t)(t + q) * BS] = spk;
            o_tr[(size_t)(t + q) * BS]  = tr;
        }
    }
}

/* ------------------------------------------------------------------ */
extern "C" void kernel_launch(void* const* d_in, const int* in_sizes, int n_in,
                              void* d_out, int out_size)
{
    const float* input_signal = (const float*)d_in[0];
    const float* error_signal = (const float*)d_in[1];
    const float* W_err        = (const float*)d_in[2];
    float* out = (float*)d_out;

    dim3 gemm_grid((S_DIM + BN - 1) / BN, M_DIM / BM);  /* 4 x 800 */
    spncn_gemm_kernel<<<gemm_grid, 256>>>(error_signal, W_err, input_signal);

    spncn_scan_kernel<<<(BS + 127) / 128, 128>>>(out);
}